// round 15
// baseline (speedup 1.0000x reference)
#include <cuda_runtime.h>
#include <cuda_fp16.h>
#include <cstdint>

#define BATCH 256
#define ISZ   512
#define STEPS 256
#define HID   512
#define GH    1536
#define NCTA  128
#define MROWS (STEPS * BATCH)     // 65536

// ---------------- scratch ----------------
__device__ __half g_x16[(size_t)MROWS * ISZ];
__device__ __half g_h16[2][BATCH * HID];
__device__ unsigned g_bg_cnt[4];
__device__ unsigned g_qcnt[512];       // [bg][q] at (bg*4+q)*32, 128B apart

// ---------------- helpers ----------------
__device__ __forceinline__ uint32_t smem_to_u32(const void* p) {
    uint32_t a;
    asm("{ .reg .u64 t; cvta.to.shared.u64 t, %1; cvt.u32.u64 %0, t; }" : "=r"(a) : "l"(p));
    return a;
}
__device__ __forceinline__ void cp16(uint32_t dst, const void* src) {
    asm volatile("cp.async.cg.shared.global [%0], [%1], 16;" :: "r"(dst), "l"(src));
}
#define CP_COMMIT() asm volatile("cp.async.commit_group;" ::: "memory")
#define CP_WAIT(n)  asm volatile("cp.async.wait_group %0;" :: "n"(n) : "memory")

#define BARC() asm volatile("bar.sync 1, 256;" ::: "memory")   // consumer warps 0-7
#define BARP() asm volatile("bar.sync 2, 128;" ::: "memory")   // producer warps 8-11
#define BARA() asm volatile("bar.sync 3, 384;" ::: "memory")   // whole CTA

__device__ __forceinline__ void ldsm_x4(uint32_t addr, uint32_t r[4]) {
    asm volatile("ldmatrix.sync.aligned.m8n8.x4.shared.b16 {%0,%1,%2,%3}, [%4];"
                 : "=r"(r[0]), "=r"(r[1]), "=r"(r[2]), "=r"(r[3]) : "r"(addr));
}
__device__ __forceinline__ void ldsm_x2(uint32_t addr, uint32_t r[2]) {
    asm volatile("ldmatrix.sync.aligned.m8n8.x2.shared.b16 {%0,%1}, [%2];"
                 : "=r"(r[0]), "=r"(r[1]) : "r"(addr));
}
__device__ __forceinline__ void mma_f16(float d[4], const uint32_t a[4], const uint32_t b[2]) {
    asm volatile("mma.sync.aligned.m16n8k16.row.col.f32.f16.f16.f32 "
                 "{%0,%1,%2,%3}, {%4,%5,%6,%7}, {%8,%9}, {%0,%1,%2,%3};"
                 : "+f"(d[0]), "+f"(d[1]), "+f"(d[2]), "+f"(d[3])
                 : "r"(a[0]), "r"(a[1]), "r"(a[2]), "r"(a[3]), "r"(b[0]), "r"(b[1]));
}
__device__ __forceinline__ float fast_sigmoid(float v) {
    return __fdividef(1.f, 1.f + __expf(-v));
}
__device__ __forceinline__ float fast_tanh(float v) {
    float e = __expf(-2.f * v);
    return __fdividef(1.f - e, 1.f + e);
}
__device__ __forceinline__ void pollq(int bg, int q, unsigned target) {
    const unsigned* p = &g_qcnt[(bg * 4 + q) * 32];
    unsigned v;
    do {
        asm volatile("ld.global.acquire.gpu.u32 %0, [%1];" : "=r"(v) : "l"(p) : "memory");
    } while (v < target);
}

// ---------------- x [B][I][S] -> g_x16 [(s*B+b)][i] fp16 (+ counter reset) ---------
__global__ void k_x_transpose(const float* __restrict__ x) {
    __shared__ float tile[32][33];
    int s0 = blockIdx.x * 32;
    int i0 = blockIdx.y * 32;
    int b  = blockIdx.z;
    int tx = threadIdx.x, ty = threadIdx.y;
    if (blockIdx.x == 0 && blockIdx.y == 0 && blockIdx.z == 0) {
        int t = ty * 32 + tx;
        if (t < 4) g_bg_cnt[t] = 0;
        g_qcnt[t] = 0;
        g_qcnt[t + 256] = 0;
    }
    #pragma unroll
    for (int j = 0; j < 4; ++j)
        tile[ty + 8 * j][tx] = x[((size_t)b * ISZ + i0 + ty + 8 * j) * STEPS + s0 + tx];
    __syncthreads();
    #pragma unroll
    for (int j = 0; j < 4; ++j) {
        int s = s0 + ty + 8 * j;
        float v = tile[tx][ty + 8 * j];
        g_x16[((size_t)s * BATCH + b) * ISZ + i0 + tx] = __float2half_rn(v);
    }
}

// ---------------- fused persistent kernel ----------------
#define BSTR 520
#define A_OFF  0                                 // h A tile: 64 rows x 1024B
#define BW_OFF 65536                             // Whh B: 48*BSTR*2 = 49920
#define GH_OFF (BW_OFF + 48 * BSTR * 2)          // gh: 64*50*4
#define GH_STR 50
#define WI_OFF (GH_OFF + 64 * GH_STR * 4)        // Wih B: 49920
#define XB_OFF (WI_OFF + 48 * BSTR * 2)          // x bufs: 2 x 16384
#define GI_OFF (XB_OFF + 2 * 16384)              // gi bufs: 2 x 64*56*2
#define GI_STR 56
#define FUSED_SMEM (GI_OFF + 2 * 64 * GI_STR * 2)  // 225280

__device__ __forceinline__ uint32_t a_off(int row, int kb) {
    uint32_t u = ((uint32_t)kb >> 3) ^ (row & 7);
    return (uint32_t)row * 1024 + u * 16;
}
__device__ __forceinline__ uint32_t x_off(int row, int kb) {
    uint32_t unit = (uint32_t)kb >> 3;
    uint32_t su = (unit & 8) | ((unit ^ (uint32_t)row) & 7);
    return (uint32_t)row * 256 + su * 16;
}

__device__ __forceinline__ void cntbar(int bg, unsigned target) {
    BARC();
    if (threadIdx.x == 0) {
        asm volatile("red.release.gpu.global.add.u32 [%0], %1;"
                     :: "l"(&g_bg_cnt[bg]), "r"(1u) : "memory");
        unsigned v;
        do {
            asm volatile("ld.global.acquire.gpu.u32 %0, [%1];"
                         : "=r"(v) : "l"(&g_bg_cnt[bg]) : "memory");
        } while (v < target);
    }
    BARC();
}

__global__ void __launch_bounds__(384, 1) k_fused(
    const float* __restrict__ wih, const float* __restrict__ whh,
    const float* __restrict__ bih, const float* __restrict__ bhh,
    float* __restrict__ out)
{
    extern __shared__ char smem[];
    uint32_t sb = smem_to_u32(smem);
    float* gh = (float*)(smem + GH_OFF);

    const int cta = blockIdx.x;
    const int cg  = cta & 31;
    const int bg0 = cta >> 5;
    const int tid = threadIdx.x;
    const int lane = tid & 31;
    const int wid = tid >> 5;

    const int t4 = lane >> 3;
    const int arow = (t4 & 1) * 8 + (lane & 7);
    const int acol = (t4 >> 1) * 8;
    const int brow = (t4 >> 1) * 8 + (lane & 7);
    const int bcol = (t4 & 1) * 8;
    const int brow2 = lane & 7;
    const int bcol2 = ((lane >> 3) & 1) * 8;

    // ---- init: both weight slices -> fp16 smem (all 384 threads) ----
    for (int idx = tid; idx < 48 * 128; idx += 384) {
        int r = idx >> 7;
        int kq = idx & 127;
        int g = r >> 4, c = r & 15;
        float4 vh = *(const float4*)(whh + (size_t)(g * HID + cg * 16 + c) * HID + kq * 4);
        float4 vi = *(const float4*)(wih + (size_t)(g * HID + cg * 16 + c) * ISZ + kq * 4);
        __half h4[4], i4[4];
        h4[0] = __float2half_rn(vh.x); h4[1] = __float2half_rn(vh.y);
        h4[2] = __float2half_rn(vh.z); h4[3] = __float2half_rn(vh.w);
        i4[0] = __float2half_rn(vi.x); i4[1] = __float2half_rn(vi.y);
        i4[2] = __float2half_rn(vi.z); i4[3] = __float2half_rn(vi.w);
        *(uint2*)(smem + BW_OFF + r * (BSTR * 2) + kq * 8) = *(uint2*)h4;
        *(uint2*)(smem + WI_OFF + r * (BSTR * 2) + kq * 8) = *(uint2*)i4;
    }
    if (tid < 128) {
        uint4 z = make_uint4(0, 0, 0, 0);
        *(uint4*)((char*)g_h16[0] + ((size_t)cta * 128 + tid) * 16) = z;
    }
    __syncthreads();

    if (wid < 8) {
        // ================= CONSUMER =================
        const int wm = wid & 3;
        const int wn = wid >> 2;
        const int gb = tid >> 2;
        const int cq = tid & 3;
        const int c0 = cq * 4;
        const int gcol0 = cg * 16 + c0;
        const int myq = cg >> 3;
        float brt[4], bzt[4], bni[4], bnh[4];
        #pragma unroll
        for (int i = 0; i < 4; ++i) {
            brt[i] = bih[gcol0 + i] + bhh[gcol0 + i];
            bzt[i] = bih[HID + gcol0 + i] + bhh[HID + gcol0 + i];
            bni[i] = bih[2 * HID + gcol0 + i];
            bnh[i] = bhh[2 * HID + gcol0 + i];
        }
        float h_old[4] = {0.f, 0.f, 0.f, 0.f};

        cntbar(bg0, 32u);   // startup: h zeros + counters visible

        const uint32_t bof = sb + BW_OFF;
        const int nb = wn * 24;
        const int bglob = bg0 * 64 + gb;

        for (int s = 0; s < STEPS; ++s) {
            const __half* hsrc = g_h16[s & 1];
            const unsigned tgt = 8u * (unsigned)s;

            // quarter-gated A issue: q0,q1 now; q2,q3 after MMA chunk0
            if (s > 0 && tid == 0) { pollq(bg0, 0, tgt); pollq(bg0, 1, tgt); }
            BARC();
            #pragma unroll
            for (int pre = 0; pre < 2; ++pre) {
                #pragma unroll
                for (int i = 0; i < 4; ++i) {
                    int lin = tid + 256 * i;
                    int row = lin >> 4;
                    int kb = pre * 128 + (lin & 15) * 8;
                    cp16(sb + A_OFF + a_off(row, kb),
                         hsrc + (size_t)(bg0 * 64 + row) * HID + kb);
                }
                CP_COMMIT();
            }

            float acc[3][4];
            #pragma unroll
            for (int j = 0; j < 3; ++j)
                #pragma unroll
                for (int v = 0; v < 4; ++v) acc[j][v] = 0.f;

            // MMA chunk 0
            CP_WAIT(1); BARC();
            #pragma unroll
            for (int t = 0; t < 8; ++t) {
                const int kk = t * 16;
                uint32_t Ax[4], Bx[3][2];
                ldsm_x4(sb + A_OFF + a_off(wm * 16 + arow, kk + acol), Ax);
                {
                    uint32_t q[4];
                    uint32_t r16 = (nb + brow) * (BSTR * 2) + (kk + bcol) * 2;
                    ldsm_x4(bof + r16, q);
                    Bx[0][0] = q[0]; Bx[0][1] = q[1];
                    Bx[1][0] = q[2]; Bx[1][1] = q[3];
                    uint32_t r8 = (nb + 16 + brow2) * (BSTR * 2) + (kk + bcol2) * 2;
                    ldsm_x2(bof + r8, Bx[2]);
                }
                #pragma unroll
                for (int nt = 0; nt < 3; ++nt)
                    mma_f16(acc[nt], Ax, Bx[nt]);
            }

            // gate quarters 2,3 and issue chunks 2,3
            if (s > 0 && tid == 0) { pollq(bg0, 2, tgt); pollq(bg0, 3, tgt); }
            BARC();
            #pragma unroll
            for (int pre = 2; pre < 4; ++pre) {
                #pragma unroll
                for (int i = 0; i < 4; ++i) {
                    int lin = tid + 256 * i;
                    int row = lin >> 4;
                    int kb = pre * 128 + (lin & 15) * 8;
                    cp16(sb + A_OFF + a_off(row, kb),
                         hsrc + (size_t)(bg0 * 64 + row) * HID + kb);
                }
                CP_COMMIT();
            }

            // MMA chunks 1..3
            #pragma unroll
            for (int kc = 1; kc < 4; ++kc) {
                if (kc == 1)      { CP_WAIT(2); }
                else if (kc == 2) { CP_WAIT(1); }
                else              { CP_WAIT(0); }
                BARC();
                #pragma unroll
                for (int t = 0; t < 8; ++t) {
                    const int kk = kc * 128 + t * 16;
                    uint32_t Ax[4], Bx[3][2];
                    ldsm_x4(sb + A_OFF + a_off(wm * 16 + arow, kk + acol), Ax);
                    {
                        uint32_t q[4];
                        uint32_t r16 = (nb + brow) * (BSTR * 2) + (kk + bcol) * 2;
                        ldsm_x4(bof + r16, q);
                        Bx[0][0] = q[0]; Bx[0][1] = q[1];
                        Bx[1][0] = q[2]; Bx[1][1] = q[3];
                        uint32_t r8 = (nb + 16 + brow2) * (BSTR * 2) + (kk + bcol2) * 2;
                        ldsm_x2(bof + r8, Bx[2]);
                    }
                    #pragma unroll
                    for (int nt = 0; nt < 3; ++nt)
                        mma_f16(acc[nt], Ax, Bx[nt]);
                }
            }

            // gh fragments
            {
                int row0 = wm * 16 + (lane >> 2);
                int col0 = nb + (lane & 3) * 2;
                #pragma unroll
                for (int nt = 0; nt < 3; ++nt) {
                    *(float2*)(gh + row0 * GH_STR + col0 + nt * 8) = make_float2(acc[nt][0], acc[nt][1]);
                    *(float2*)(gh + (row0 + 8) * GH_STR + col0 + nt * 8) = make_float2(acc[nt][2], acc[nt][3]);
                }
            }

            BARA();   // gh done + gi[s] ready

            {
                const __half* gib = (const __half*)(smem + GI_OFF + (s & 1) * (64 * GI_STR * 2));
                __half h16v[4];
                float hnew4[4];
                #pragma unroll
                for (int i = 0; i < 4; ++i) {
                    int c = c0 + i;
                    float gr = __half2float(gib[gb * GI_STR + 0 * 16 + c]);
                    float gz = __half2float(gib[gb * GI_STR + 1 * 16 + c]);
                    float gn = __half2float(gib[gb * GI_STR + 2 * 16 + c]);
                    float ar = gh[gb * GH_STR + 0 * 16 + c];
                    float az = gh[gb * GH_STR + 1 * 16 + c];
                    float an = gh[gb * GH_STR + 2 * 16 + c];
                    float rg = fast_sigmoid(gr + ar + brt[i]);
                    float zg = fast_sigmoid(gz + az + bzt[i]);
                    float ng = fast_tanh(gn + bni[i] + rg * (an + bnh[i]));
                    float hnew = (1.f - zg) * ng + zg * h_old[i];
                    h_old[i] = hnew;
                    hnew4[i] = hnew;
                    h16v[i] = __float2half_rn(hnew);
                }
                size_t ho = (size_t)bglob * HID + gcol0;
                *(uint2*)(g_h16[(s + 1) & 1] + ho) = *(uint2*)h16v;
                if (s == STEPS - 1)
                    *(float4*)(out + ho) = *(float4*)hnew4;
            }

            // publish own quarter (release covers all threads' h16 stores via BARC)
            BARC();
            if (tid == 0 && s < STEPS - 1) {
                asm volatile("red.release.gpu.global.add.u32 [%0], %1;"
                             :: "l"(&g_qcnt[(bg0 * 4 + myq) * 32]), "r"(1u) : "memory");
            }
        }
    } else {
        // ================= PRODUCER (unchanged) =================
        const int p   = tid - 256;
        const int pw  = wid - 8;
        const int pwm = pw & 1;
        const int pwn = pw >> 1;
        const uint32_t wif = sb + WI_OFF;
        const int nb_p = pwn * 24;

        for (int s = 0; s < STEPS; ++s) {
            const size_t xrow0 = (size_t)s * BATCH + bg0 * 64;

            #pragma unroll
            for (int pre = 0; pre < 2; ++pre) {
                #pragma unroll
                for (int i = 0; i < 8; ++i) {
                    int lin = p + 128 * i;
                    int row = lin >> 4;
                    int unit = lin & 15;
                    cp16(sb + XB_OFF + pre * 16384 + x_off(row, unit * 8),
                         g_x16 + (xrow0 + row) * ISZ + pre * 128 + unit * 8);
                }
                CP_COMMIT();
            }

            float acc[2][3][4];
            #pragma unroll
            for (int m = 0; m < 2; ++m)
                #pragma unroll
                for (int j = 0; j < 3; ++j)
                    #pragma unroll
                    for (int v = 0; v < 4; ++v) acc[m][j][v] = 0.f;

            #pragma unroll
            for (int kc = 0; kc < 4; ++kc) {
                if (kc < 3) CP_WAIT(1); else CP_WAIT(0);
                BARP();
                const uint32_t xb = sb + XB_OFF + (kc & 1) * 16384;

                #pragma unroll
                for (int t = 0; t < 8; ++t) {
                    const int kkl = t * 16;
                    const int kk  = kc * 128 + kkl;
                    uint32_t Bx[3][2];
                    {
                        uint32_t q[4];
                        uint32_t r16 = (nb_p + brow) * (BSTR * 2) + (kk + bcol) * 2;
                        ldsm_x4(wif + r16, q);
                        Bx[0][0] = q[0]; Bx[0][1] = q[1];
                        Bx[1][0] = q[2]; Bx[1][1] = q[3];
                        uint32_t r8 = (nb_p + 16 + brow2) * (BSTR * 2) + (kk + bcol2) * 2;
                        ldsm_x2(wif + r8, Bx[2]);
                    }
                    #pragma unroll
                    for (int mt = 0; mt < 2; ++mt) {
                        uint32_t Ax[4];
                        int rr = pwm * 32 + mt * 16 + arow;
                        ldsm_x4(xb + x_off(rr, kkl + acol), Ax);
                        #pragma unroll
                        for (int nt = 0; nt < 3; ++nt)
                            mma_f16(acc[mt][nt], Ax, Bx[nt]);
                    }
                }
                BARP();
                if (kc < 2) {
                    int pre = kc + 2;
                    #pragma unroll
                    for (int i = 0; i < 8; ++i) {
                        int lin = p + 128 * i;
                        int row = lin >> 4;
                        int unit = lin & 15;
                        cp16(sb + XB_OFF + (pre & 1) * 16384 + x_off(row, unit * 8),
                             g_x16 + (xrow0 + row) * ISZ + pre * 128 + unit * 8);
                    }
                    CP_COMMIT();
                }
            }

            {
                __half* gob = (__half*)(smem + GI_OFF + (s & 1) * (64 * GI_STR * 2));
                int col0 = nb_p + (lane & 3) * 2;
                #pragma unroll
                for (int mt = 0; mt < 2; ++mt) {
                    int row0 = pwm * 32 + mt * 16 + (lane >> 2);
                    #pragma unroll
                    for (int nt = 0; nt < 3; ++nt) {
                        *(__half2*)(gob + row0 * GI_STR + col0 + nt * 8) =
                            __floats2half2_rn(acc[mt][nt][0], acc[mt][nt][1]);
                        *(__half2*)(gob + (row0 + 8) * GI_STR + col0 + nt * 8) =
                            __floats2half2_rn(acc[mt][nt][2], acc[mt][nt][3]);
                    }
                }
            }

            BARA();
        }
    }
}

// ---------------- launcher ----------------
extern "C" void kernel_launch(void* const* d_in, const int* in_sizes, int n_in,
                              void* d_out, int out_size) {
    const float* x   = (const float*)d_in[0];
    const float* wih = (const float*)d_in[1];
    const float* whh = (const float*)d_in[2];
    const float* bih = (const float*)d_in[3];
    const float* bhh = (const float*)d_in[4];
    float* out = (float*)d_out;

    cudaFuncSetAttribute(k_fused, cudaFuncAttributeMaxDynamicSharedMemorySize,
                         FUSED_SMEM);

    k_x_transpose<<<dim3(STEPS / 32, ISZ / 32, BATCH), dim3(32, 8)>>>(x);
    k_fused<<<NCTA, 384, FUSED_SMEM>>>(wih, whh, bih, bhh, out);
}

// round 16
// speedup vs baseline: 1.2374x; 1.2374x over previous
#include <cuda_runtime.h>
#include <cuda_fp16.h>
#include <cstdint>

#define BATCH 256
#define ISZ   512
#define STEPS 256
#define HID   512
#define GH    1536
#define NCTA  128
#define MROWS (STEPS * BATCH)     // 65536

// ---------------- scratch ----------------
__device__ __half g_x16[(size_t)MROWS * ISZ];
__device__ __half g_h16[2][BATCH * HID];
__device__ unsigned g_bg_cnt[4];

// ---------------- helpers ----------------
__device__ __forceinline__ uint32_t smem_to_u32(const void* p) {
    uint32_t a;
    asm("{ .reg .u64 t; cvta.to.shared.u64 t, %1; cvt.u32.u64 %0, t; }" : "=r"(a) : "l"(p));
    return a;
}
__device__ __forceinline__ void cp16(uint32_t dst, const void* src) {
    asm volatile("cp.async.cg.shared.global [%0], [%1], 16;" :: "r"(dst), "l"(src));
}
#define CP_COMMIT() asm volatile("cp.async.commit_group;" ::: "memory")
#define CP_WAIT(n)  asm volatile("cp.async.wait_group %0;" :: "n"(n) : "memory")

#define BARC() asm volatile("bar.sync 1, 256;" ::: "memory")   // consumer warps 0-7
#define BARP() asm volatile("bar.sync 2, 128;" ::: "memory")   // producer warps 8-11
#define BARA() asm volatile("bar.sync 3, 384;" ::: "memory")   // whole CTA

__device__ __forceinline__ void ldsm_x4(uint32_t addr, uint32_t r[4]) {
    asm volatile("ldmatrix.sync.aligned.m8n8.x4.shared.b16 {%0,%1,%2,%3}, [%4];"
                 : "=r"(r[0]), "=r"(r[1]), "=r"(r[2]), "=r"(r[3]) : "r"(addr));
}
__device__ __forceinline__ void ldsm_x2(uint32_t addr, uint32_t r[2]) {
    asm volatile("ldmatrix.sync.aligned.m8n8.x2.shared.b16 {%0,%1}, [%2];"
                 : "=r"(r[0]), "=r"(r[1]) : "r"(addr));
}
__device__ __forceinline__ void mma_f16(float d[4], const uint32_t a[4], const uint32_t b[2]) {
    asm volatile("mma.sync.aligned.m16n8k16.row.col.f32.f16.f16.f32 "
                 "{%0,%1,%2,%3}, {%4,%5,%6,%7}, {%8,%9}, {%0,%1,%2,%3};"
                 : "+f"(d[0]), "+f"(d[1]), "+f"(d[2]), "+f"(d[3])
                 : "r"(a[0]), "r"(a[1]), "r"(a[2]), "r"(a[3]), "r"(b[0]), "r"(b[1]));
}
__device__ __forceinline__ float fast_sigmoid(float v) {
    return __fdividef(1.f, 1.f + __expf(-v));
}
__device__ __forceinline__ float fast_tanh(float v) {
    float e = __expf(-2.f * v);
    return __fdividef(1.f - e, 1.f + e);
}

// ---------------- x [B][I][S] -> g_x16 [(s*B+b)][i] fp16 (+ counter reset) ---------
__global__ void k_x_transpose(const float* __restrict__ x) {
    __shared__ float tile[32][33];
    int s0 = blockIdx.x * 32;
    int i0 = blockIdx.y * 32;
    int b  = blockIdx.z;
    int tx = threadIdx.x, ty = threadIdx.y;
    if (blockIdx.x == 0 && blockIdx.y == 0 && blockIdx.z == 0) {
        int t = ty * 32 + tx;
        if (t < 4) g_bg_cnt[t] = 0;
    }
    #pragma unroll
    for (int j = 0; j < 4; ++j)
        tile[ty + 8 * j][tx] = x[((size_t)b * ISZ + i0 + ty + 8 * j) * STEPS + s0 + tx];
    __syncthreads();
    #pragma unroll
    for (int j = 0; j < 4; ++j) {
        int s = s0 + ty + 8 * j;
        float v = tile[tx][ty + 8 * j];
        g_x16[((size_t)s * BATCH + b) * ISZ + i0 + tx] = __float2half_rn(v);
    }
}

// ---------------- fused persistent kernel ----------------
// 128 CTAs x 384 threads = 4 bg (64 rows) x 32 cg (16 cols x 3 gates).
// Warps 0-7: GRU consumer. Warps 8-11: gi producer (gi never touches gmem).
#define BSTR 520
#define A_OFF  0                                 // h A tile: 64 rows x 1024B
#define BW_OFF 65536                             // Whh B: 48*BSTR*2 = 49920
#define GH_OFF (BW_OFF + 48 * BSTR * 2)          // 115456; gh: 64*52*4 = 13312
#define GH_STR 52
#define WI_OFF (GH_OFF + 64 * GH_STR * 4)        // 128768; Wih B: 49920
#define XB_OFF (WI_OFF + 48 * BSTR * 2)          // 178688; x bufs: 2 x 16384
#define GI_OFF (XB_OFF + 2 * 16384)              // 211456; gi bufs: 2 x 64*56*2
#define GI_STR 56
#define FUSED_SMEM (GI_OFF + 2 * 64 * GI_STR * 2)  // 225792

__device__ __forceinline__ uint32_t a_off(int row, int kb) {
    uint32_t u = ((uint32_t)kb >> 3) ^ (row & 7);
    return (uint32_t)row * 1024 + u * 16;
}
__device__ __forceinline__ uint32_t x_off(int row, int kb) {
    uint32_t unit = (uint32_t)kb >> 3;
    uint32_t su = (unit & 8) | ((unit ^ (uint32_t)row) & 7);
    return (uint32_t)row * 256 + su * 16;
}

__device__ __forceinline__ void cntbar(int bg, unsigned target) {
    BARC();
    if (threadIdx.x == 0) {
        asm volatile("red.release.gpu.global.add.u32 [%0], %1;"
                     :: "l"(&g_bg_cnt[bg]), "r"(1u) : "memory");
        unsigned v;
        do {
            asm volatile("ld.global.acquire.gpu.u32 %0, [%1];"
                         : "=r"(v) : "l"(&g_bg_cnt[bg]) : "memory");
        } while (v < target);
    }
    BARC();
}

__global__ void __launch_bounds__(384, 1) k_fused(
    const float* __restrict__ wih, const float* __restrict__ whh,
    const float* __restrict__ bih, const float* __restrict__ bhh,
    float* __restrict__ out)
{
    extern __shared__ char smem[];
    uint32_t sb = smem_to_u32(smem);
    float* gh = (float*)(smem + GH_OFF);

    const int cta = blockIdx.x;
    const int cg  = cta & 31;
    const int bg0 = cta >> 5;
    const int tid = threadIdx.x;
    const int lane = tid & 31;
    const int wid = tid >> 5;

    const int t4 = lane >> 3;
    const int arow = (t4 & 1) * 8 + (lane & 7);
    const int acol = (t4 >> 1) * 8;
    const int brow = (t4 >> 1) * 8 + (lane & 7);
    const int bcol = (t4 & 1) * 8;
    const int brow2 = lane & 7;
    const int bcol2 = ((lane >> 3) & 1) * 8;

    // ---- init: both weight slices -> fp16 smem (all 384 threads) ----
    for (int idx = tid; idx < 48 * 128; idx += 384) {
        int r = idx >> 7;
        int kq = idx & 127;
        int g = r >> 4, c = r & 15;
        float4 vh = *(const float4*)(whh + (size_t)(g * HID + cg * 16 + c) * HID + kq * 4);
        float4 vi = *(const float4*)(wih + (size_t)(g * HID + cg * 16 + c) * ISZ + kq * 4);
        __half h4[4], i4[4];
        h4[0] = __float2half_rn(vh.x); h4[1] = __float2half_rn(vh.y);
        h4[2] = __float2half_rn(vh.z); h4[3] = __float2half_rn(vh.w);
        i4[0] = __float2half_rn(vi.x); i4[1] = __float2half_rn(vi.y);
        i4[2] = __float2half_rn(vi.z); i4[3] = __float2half_rn(vi.w);
        *(uint2*)(smem + BW_OFF + r * (BSTR * 2) + kq * 8) = *(uint2*)h4;
        *(uint2*)(smem + WI_OFF + r * (BSTR * 2) + kq * 8) = *(uint2*)i4;
    }
    if (tid < 128) {
        uint4 z = make_uint4(0, 0, 0, 0);
        *(uint4*)((char*)g_h16[0] + ((size_t)cta * 128 + tid) * 16) = z;
    }
    __syncthreads();

    if (wid < 8) {
        // ================= CONSUMER =================
        const int wm = wid & 3;
        const int wn = wid >> 2;
        const int gb = tid >> 2;
        const int cq = tid & 3;
        const int c0 = cq * 4;
        const int gcol0 = cg * 16 + c0;
        float brt[4], bzt[4], bni[4], bnh[4];
        #pragma unroll
        for (int i = 0; i < 4; ++i) {
            brt[i] = bih[gcol0 + i] + bhh[gcol0 + i];
            bzt[i] = bih[HID + gcol0 + i] + bhh[HID + gcol0 + i];
            bni[i] = bih[2 * HID + gcol0 + i];
            bnh[i] = bhh[2 * HID + gcol0 + i];
        }
        float h_old[4] = {0.f, 0.f, 0.f, 0.f};

        cntbar(bg0, 32u);   // startup: h zeros visible across the bg

        const uint32_t bof = sb + BW_OFF;
        const int nb = wn * 24;
        const int bglob = bg0 * 64 + gb;

        for (int s = 0; s < STEPS; ++s) {
            const __half* hsrc = g_h16[s & 1];

            // issue A in 2 k-halves (32KB each; 8 cp16/thread per half)
            #pragma unroll
            for (int pre = 0; pre < 2; ++pre) {
                #pragma unroll
                for (int i = 0; i < 8; ++i) {
                    int lin = tid + 256 * i;            // 0..2047
                    int row = lin >> 5;                 // 0..63
                    int kb = pre * 256 + (lin & 31) * 8;
                    cp16(sb + A_OFF + a_off(row, kb),
                         hsrc + (size_t)(bg0 * 64 + row) * HID + kb);
                }
                CP_COMMIT();
            }

            float acc[3][4];
            #pragma unroll
            for (int j = 0; j < 3; ++j)
                #pragma unroll
                for (int v = 0; v < 4; ++v) acc[j][v] = 0.f;

            #pragma unroll
            for (int kc = 0; kc < 2; ++kc) {
                if (kc == 0) CP_WAIT(1); else CP_WAIT(0);
                BARC();
                #pragma unroll
                for (int t = 0; t < 16; ++t) {
                    const int kk = kc * 256 + t * 16;
                    uint32_t Ax[4], Bx[3][2];
                    ldsm_x4(sb + A_OFF + a_off(wm * 16 + arow, kk + acol), Ax);
                    {
                        uint32_t q[4];
                        uint32_t r16 = (nb + brow) * (BSTR * 2) + (kk + bcol) * 2;
                        ldsm_x4(bof + r16, q);
                        Bx[0][0] = q[0]; Bx[0][1] = q[1];
                        Bx[1][0] = q[2]; Bx[1][1] = q[3];
                        uint32_t r8 = (nb + 16 + brow2) * (BSTR * 2) + (kk + bcol2) * 2;
                        ldsm_x2(bof + r8, Bx[2]);
                    }
                    #pragma unroll
                    for (int nt = 0; nt < 3; ++nt)
                        mma_f16(acc[nt], Ax, Bx[nt]);
                }
            }

            // gh fragments (aligned float2 stores; GH_STR=52 -> float4-aligned rows)
            {
                int row0 = wm * 16 + (lane >> 2);
                int col0 = nb + (lane & 3) * 2;
                #pragma unroll
                for (int nt = 0; nt < 3; ++nt) {
                    *(float2*)(gh + row0 * GH_STR + col0 + nt * 8) = make_float2(acc[nt][0], acc[nt][1]);
                    *(float2*)(gh + (row0 + 8) * GH_STR + col0 + nt * 8) = make_float2(acc[nt][2], acc[nt][3]);
                }
            }

            BARA();   // gh done + gi[s] ready

            {
                const __half* gib = (const __half*)(smem + GI_OFF + (s & 1) * (64 * GI_STR * 2));
                float4 ghr = *(const float4*)(gh + gb * GH_STR + 0 * 16 + c0);
                float4 ghz = *(const float4*)(gh + gb * GH_STR + 1 * 16 + c0);
                float4 ghn = *(const float4*)(gh + gb * GH_STR + 2 * 16 + c0);
                float arv[4] = {ghr.x, ghr.y, ghr.z, ghr.w};
                float azv[4] = {ghz.x, ghz.y, ghz.z, ghz.w};
                float anv[4] = {ghn.x, ghn.y, ghn.z, ghn.w};
                __half h16v[4];
                float hnew4[4];
                #pragma unroll
                for (int i = 0; i < 4; ++i) {
                    int c = c0 + i;
                    float gr = __half2float(gib[gb * GI_STR + 0 * 16 + c]);
                    float gz = __half2float(gib[gb * GI_STR + 1 * 16 + c]);
                    float gn = __half2float(gib[gb * GI_STR + 2 * 16 + c]);
                    float rg = fast_sigmoid(gr + arv[i] + brt[i]);
                    float zg = fast_sigmoid(gz + azv[i] + bzt[i]);
                    float ng = fast_tanh(gn + bni[i] + rg * (anv[i] + bnh[i]));
                    float hnew = (1.f - zg) * ng + zg * h_old[i];
                    h_old[i] = hnew;
                    hnew4[i] = hnew;
                    h16v[i] = __float2half_rn(hnew);
                }
                size_t ho = (size_t)bglob * HID + gcol0;
                *(uint2*)(g_h16[(s + 1) & 1] + ho) = *(uint2*)h16v;
                if (s == STEPS - 1)
                    *(float4*)(out + ho) = *(float4*)hnew4;
            }

            if (s < STEPS - 1)
                cntbar(bg0, 32u * (s + 2));   // final step: nobody polls -> skip
        }
    } else {
        // ================= PRODUCER (unchanged) =================
        const int p   = tid - 256;
        const int pw  = wid - 8;
        const int pwm = pw & 1;
        const int pwn = pw >> 1;
        const uint32_t wif = sb + WI_OFF;
        const int nb_p = pwn * 24;

        for (int s = 0; s < STEPS; ++s) {
            const size_t xrow0 = (size_t)s * BATCH + bg0 * 64;

            #pragma unroll
            for (int pre = 0; pre < 2; ++pre) {
                #pragma unroll
                for (int i = 0; i < 8; ++i) {
                    int lin = p + 128 * i;
                    int row = lin >> 4;
                    int unit = lin & 15;
                    cp16(sb + XB_OFF + pre * 16384 + x_off(row, unit * 8),
                         g_x16 + (xrow0 + row) * ISZ + pre * 128 + unit * 8);
                }
                CP_COMMIT();
            }

            float acc[2][3][4];
            #pragma unroll
            for (int m = 0; m < 2; ++m)
                #pragma unroll
                for (int j = 0; j < 3; ++j)
                    #pragma unroll
                    for (int v = 0; v < 4; ++v) acc[m][j][v] = 0.f;

            #pragma unroll
            for (int kc = 0; kc < 4; ++kc) {
                if (kc < 3) CP_WAIT(1); else CP_WAIT(0);
                BARP();
                const uint32_t xb = sb + XB_OFF + (kc & 1) * 16384;

                #pragma unroll
                for (int t = 0; t < 8; ++t) {
                    const int kkl = t * 16;
                    const int kk  = kc * 128 + kkl;
                    uint32_t Bx[3][2];
                    {
                        uint32_t q[4];
                        uint32_t r16 = (nb_p + brow) * (BSTR * 2) + (kk + bcol) * 2;
                        ldsm_x4(wif + r16, q);
                        Bx[0][0] = q[0]; Bx[0][1] = q[1];
                        Bx[1][0] = q[2]; Bx[1][1] = q[3];
                        uint32_t r8 = (nb_p + 16 + brow2) * (BSTR * 2) + (kk + bcol2) * 2;
                        ldsm_x2(wif + r8, Bx[2]);
                    }
                    #pragma unroll
                    for (int mt = 0; mt < 2; ++mt) {
                        uint32_t Ax[4];
                        int rr = pwm * 32 + mt * 16 + arow;
                        ldsm_x4(xb + x_off(rr, kkl + acol), Ax);
                        #pragma unroll
                        for (int nt = 0; nt < 3; ++nt)
                            mma_f16(acc[mt][nt], Ax, Bx[nt]);
                    }
                }
                BARP();
                if (kc < 2) {
                    int pre = kc + 2;
                    #pragma unroll
                    for (int i = 0; i < 8; ++i) {
                        int lin = p + 128 * i;
                        int row = lin >> 4;
                        int unit = lin & 15;
                        cp16(sb + XB_OFF + (pre & 1) * 16384 + x_off(row, unit * 8),
                             g_x16 + (xrow0 + row) * ISZ + pre * 128 + unit * 8);
                    }
                    CP_COMMIT();
                }
            }

            {
                __half* gob = (__half*)(smem + GI_OFF + (s & 1) * (64 * GI_STR * 2));
                int col0 = nb_p + (lane & 3) * 2;
                #pragma unroll
                for (int mt = 0; mt < 2; ++mt) {
                    int row0 = pwm * 32 + mt * 16 + (lane >> 2);
                    #pragma unroll
                    for (int nt = 0; nt < 3; ++nt) {
                        *(__half2*)(gob + row0 * GI_STR + col0 + nt * 8) =
                            __floats2half2_rn(acc[mt][nt][0], acc[mt][nt][1]);
                        *(__half2*)(gob + (row0 + 8) * GI_STR + col0 + nt * 8) =
                            __floats2half2_rn(acc[mt][nt][2], acc[mt][nt][3]);
                    }
                }
            }

            BARA();
        }
    }
}

// ---------------- launcher ----------------
extern "C" void kernel_launch(void* const* d_in, const int* in_sizes, int n_in,
                              void* d_out, int out_size) {
    const float* x   = (const float*)d_in[0];
    const float* wih = (const float*)d_in[1];
    const float* whh = (const float*)d_in[2];
    const float* bih = (const float*)d_in[3];
    const float* bhh = (const float*)d_in[4];
    float* out = (float*)d_out;

    cudaFuncSetAttribute(k_fused, cudaFuncAttributeMaxDynamicSharedMemorySize,
                         FUSED_SMEM);

    k_x_transpose<<<dim3(STEPS / 32, ISZ / 32, BATCH), dim3(32, 8)>>>(x);
    k_fused<<<NCTA, 384, FUSED_SMEM>>>(wih, whh, bih, bhh, out);
}